// round 13
// baseline (speedup 1.0000x reference)
#include <cuda_runtime.h>
#include <cuda_bf16.h>
#include <math.h>

// Problem constants (shapes fixed for this problem instance)
#define BB 64           // batch
#define DD 1024         // hidden dim
#define VV 32000        // vocab
#define VP 33152        // padded vocab = 148 * 224
#define GG 4096         // 4*D
#define SS 128          // selected seq len
#define NTL 148         // logits blocks (224 padded vocab rows each)

// ---------------- persistent device scratch (no runtime allocs) ----------------
__device__ float g_c[BB * DD];
__device__ float g_gates[BB * GG];
__device__ float g_cs[BB];
__device__ float g_selp[BB * 8];
__device__ unsigned long long g_cand[NTL * BB];

// split-bf16 operands
__device__ __nv_bfloat16 g_Ah[BB * 2048];       // [b][0:1024]=emb, [1024:2048]=h
__device__ __nv_bfloat16 g_Al[BB * 2048];
__device__ __nv_bfloat16 g_Wo_hi[VP * DD];      // zero-padded rows >= VV
__device__ __nv_bfloat16 g_Wo_lo[VP * DD];
__device__ __nv_bfloat16 g_Wg_hi[GG * 2048];    // concat(W_ih | W_hh) along K
__device__ __nv_bfloat16 g_Wg_lo[GG * 2048];

// ---------------- helpers ----------------
__device__ __forceinline__ unsigned enc_f(float f) {
    unsigned u = __float_as_uint(f);
    return (u & 0x80000000u) ? ~u : (u | 0x80000000u);
}
__device__ __forceinline__ float sigf(float x) { return 1.0f / (1.0f + expf(-x)); }

__device__ __forceinline__ void cpa8(unsigned s, const void* g) {
    asm volatile("cp.async.ca.shared.global [%0], [%1], 8;" :: "r"(s), "l"(g));
}
__device__ __forceinline__ void cpa16(unsigned s, const void* g) {
    asm volatile("cp.async.cg.shared.global [%0], [%1], 16;" :: "r"(s), "l"(g));
}
#define CPA_COMMIT() asm volatile("cp.async.commit_group;")
#define CPA_WAIT(n)  asm volatile("cp.async.wait_group %0;" :: "n"(n))

__device__ __forceinline__ void mma16816(float* c, const unsigned* a,
                                         unsigned b0, unsigned b1) {
    asm volatile(
        "mma.sync.aligned.m16n8k16.row.col.f32.bf16.bf16.f32 "
        "{%0,%1,%2,%3}, {%4,%5,%6,%7}, {%8,%9}, {%0,%1,%2,%3};"
        : "+f"(c[0]), "+f"(c[1]), "+f"(c[2]), "+f"(c[3])
        : "r"(a[0]), "r"(a[1]), "r"(a[2]), "r"(a[3]), "r"(b0), "r"(b1));
}

__device__ __forceinline__ void ldsm4(unsigned& r0, unsigned& r1,
                                      unsigned& r2, unsigned& r3, unsigned addr) {
    asm volatile("ldmatrix.sync.aligned.m8n8.x4.shared.b16 {%0,%1,%2,%3}, [%4];"
                 : "=r"(r0), "=r"(r1), "=r"(r2), "=r"(r3) : "r"(addr));
}
__device__ __forceinline__ void ldsm2(unsigned& r0, unsigned& r1, unsigned addr) {
    asm volatile("ldmatrix.sync.aligned.m8n8.x2.shared.b16 {%0,%1}, [%2];"
                 : "=r"(r0), "=r"(r1) : "r"(addr));
}

__device__ __forceinline__ void split2(float x, __nv_bfloat16& hi, __nv_bfloat16& lo) {
    hi = __float2bfloat16(x);
    lo = __float2bfloat16(x - __bfloat162float(hi));
}
__device__ __forceinline__ unsigned smem_u32(const void* p) {
    return (unsigned)__cvta_generic_to_shared(p);
}

// ---------------- weight splitting (once per call, x4 vectorized) ----------------
__global__ void k_split_wo(const float* __restrict__ Wo) {
    size_t i = ((size_t)blockIdx.x * 256 + threadIdx.x) * 4;
    if (i < (size_t)VV * DD) {
        float4 v = *(const float4*)(Wo + i);
        __nv_bfloat16 h0,l0,h1,l1,h2,l2,h3,l3;
        split2(v.x,h0,l0); split2(v.y,h1,l1); split2(v.z,h2,l2); split2(v.w,h3,l3);
        uint2 ph, pl;
        ph.x = (unsigned)__bfloat16_as_ushort(h0) | ((unsigned)__bfloat16_as_ushort(h1) << 16);
        ph.y = (unsigned)__bfloat16_as_ushort(h2) | ((unsigned)__bfloat16_as_ushort(h3) << 16);
        pl.x = (unsigned)__bfloat16_as_ushort(l0) | ((unsigned)__bfloat16_as_ushort(l1) << 16);
        pl.y = (unsigned)__bfloat16_as_ushort(l2) | ((unsigned)__bfloat16_as_ushort(l3) << 16);
        *(uint2*)(g_Wo_hi + i) = ph;
        *(uint2*)(g_Wo_lo + i) = pl;
    } else if (i < (size_t)VP * DD) {
        uint2 z = make_uint2(0u, 0u);
        *(uint2*)(g_Wo_hi + i) = z;
        *(uint2*)(g_Wo_lo + i) = z;
    }
}
__global__ void k_split_wg(const float* __restrict__ Wih,
                           const float* __restrict__ Whh) {
    size_t i = ((size_t)blockIdx.x * 256 + threadIdx.x) * 4;
    if (i < (size_t)GG * 2048) {
        int j = (int)(i >> 11), k = (int)(i & 2047);
        const float* src = (k < DD) ? (Wih + (size_t)j * DD + k)
                                    : (Whh + (size_t)j * DD + k - DD);
        float4 v = *(const float4*)src;
        __nv_bfloat16 h0,l0,h1,l1,h2,l2,h3,l3;
        split2(v.x,h0,l0); split2(v.y,h1,l1); split2(v.z,h2,l2); split2(v.w,h3,l3);
        uint2 ph, pl;
        ph.x = (unsigned)__bfloat16_as_ushort(h0) | ((unsigned)__bfloat16_as_ushort(h1) << 16);
        ph.y = (unsigned)__bfloat16_as_ushort(h2) | ((unsigned)__bfloat16_as_ushort(h3) << 16);
        pl.x = (unsigned)__bfloat16_as_ushort(l0) | ((unsigned)__bfloat16_as_ushort(l1) << 16);
        pl.y = (unsigned)__bfloat16_as_ushort(l2) | ((unsigned)__bfloat16_as_ushort(l3) << 16);
        *(uint2*)(g_Wg_hi + i) = ph;
        *(uint2*)(g_Wg_lo + i) = pl;
    }
}

// ---------------- init: zero c and A buffers ----------------
__global__ void k_init() {
    int i = blockIdx.x * 256 + threadIdx.x;
    if (i < BB * DD) g_c[i] = 0.0f;
    if (i < BB * 2048) { g_Ah[i] = __float2bfloat16(0.0f); g_Al[i] = __float2bfloat16(0.0f); }
}

// ---------------- selterm partials: 512 blocks of (b, d-slice of 128) ----------------
__global__ void k_selterm1(const float* __restrict__ selected,
                           const float* __restrict__ Wc) {
    int b = blockIdx.x >> 3, s = blockIdx.x & 7, tid = threadIdx.x;  // 128 threads
    int d = s * 128 + tid;
    const float* p = selected + (size_t)b * SS * DD + d;
    float sum = 0.0f;
    #pragma unroll 4
    for (int si = 0; si < SS; ++si) sum += p[(size_t)si * DD];
    float v = Wc[DD + d] * (sum * (1.0f / (float)SS));
    __shared__ float sr[128];
    sr[tid] = v; __syncthreads();
    for (int st = 64; st > 0; st >>= 1) {
        if (tid < st) sr[tid] += sr[tid + st];
        __syncthreads();
    }
    if (tid == 0) g_selp[b * 8 + s] = sr[0];
}

// ---------------- tok: argmax reduce (t>0) + embedding gather/split ----------------
__global__ void k_tok(const float* __restrict__ emb_W, int t) {
    int b = blockIdx.x, tid = threadIdx.x;
    __shared__ unsigned long long sk[256];
    __shared__ int s_j;
    if (t == 0) {
        if (tid == 0) s_j = 0;                // tok0 = 0 (PAD row is zeros)
    } else {
        unsigned long long best = 0ull;
        for (int i = tid; i < NTL; i += 256) {
            unsigned long long v = g_cand[i * BB + b];
            if (v > best) best = v;
        }
        sk[tid] = best; __syncthreads();
        for (int s = 128; s > 0; s >>= 1) {
            if (tid < s && sk[tid + s] > sk[tid]) sk[tid] = sk[tid + s];
            __syncthreads();
        }
        if (tid == 0) s_j = (int)(0xFFFFFFFFu - (unsigned)(sk[0] & 0xFFFFFFFFull));
    }
    __syncthreads();
    int j = s_j;
    const float4 e4 = *(const float4*)(emb_W + (size_t)j * DD + tid * 4);
    __nv_bfloat16 h0, l0, h1, l1, h2, l2, h3, l3;
    split2(e4.x, h0, l0); split2(e4.y, h1, l1);
    split2(e4.z, h2, l2); split2(e4.w, h3, l3);
    size_t o = (size_t)b * 2048 + tid * 4;
    g_Ah[o] = h0; g_Ah[o+1] = h1; g_Ah[o+2] = h2; g_Ah[o+3] = h3;
    g_Al[o] = l0; g_Al[o+1] = l1; g_Al[o+2] = l2; g_Al[o+3] = l3;
}

// ---------------- gates = A @ Wg^T (split-bf16 mma.sync, 3 passes) ----------------
// 128 blocks of 64M x 32N. K=2048, chunks of 64 (stride 72 halves in smem).
__global__ void __launch_bounds__(256) k_gates() {
    const int tid = threadIdx.x;
    const int lane = tid & 31, warp = tid >> 5;
    const int lr = lane >> 2, lc2 = (lane & 3) * 2;
    const int m0 = (warp >> 1) * 16, n0w = (warp & 1) * 16;
    const int j0 = blockIdx.x * 32;

    __shared__ __align__(16) __nv_bfloat16 sWh[2][32 * 72];
    __shared__ __align__(16) __nv_bfloat16 sWl[2][32 * 72];
    __shared__ __align__(16) __nv_bfloat16 sAh[2][64 * 72];
    __shared__ __align__(16) __nv_bfloat16 sAl[2][64 * 72];

    unsigned aWh[2], aWl[2], aAh[2], aAl[2];
    #pragma unroll
    for (int s = 0; s < 2; ++s) {
        aWh[s] = smem_u32(&sWh[s][0]);
        aWl[s] = smem_u32(&sWl[s][0]);
        aAh[s] = smem_u32(&sAh[s][0]);
        aAl[s] = smem_u32(&sAl[s][0]);
    }

    float C[2][4] = {};

    auto issue = [&](int ch, int st) {
        int k0 = ch * 64;
        #pragma unroll
        for (int i = 0; i < 2; ++i) {
            int c = tid + 256 * i;           // 512 W chunks
            int row = c >> 4, part = c & 15;
            unsigned d = (unsigned)(row * 72 + part * 4) * 2;
            size_t gsrc = (size_t)(j0 + row) * 2048 + k0 + part * 4;
            cpa8(aWh[st] + d, g_Wg_hi + gsrc);
            cpa8(aWl[st] + d, g_Wg_lo + gsrc);
        }
        #pragma unroll
        for (int i = 0; i < 4; ++i) {
            int c = tid + 256 * i;           // 1024 A chunks
            int row = c >> 4, part = c & 15;
            unsigned d = (unsigned)(row * 72 + part * 4) * 2;
            size_t gsrc = (size_t)row * 2048 + k0 + part * 4;
            cpa8(aAh[st] + d, g_Ah + gsrc);
            cpa8(aAl[st] + d, g_Al + gsrc);
        }
        CPA_COMMIT();
    };
    auto compute = [&](int st) {
        #pragma unroll
        for (int k16 = 0; k16 < 4; ++k16) {
            const int kb = k16 * 16;
            unsigned ah[4], al[4];
            #pragma unroll
            for (int r = 0; r < 4; ++r) {
                int mm = m0 + lr + (r & 1) * 8;
                int kk = kb + lc2 + (r >> 1) * 8;
                ah[r] = *(const unsigned*)&sAh[st][mm * 72 + kk];
                al[r] = *(const unsigned*)&sAl[st][mm * 72 + kk];
            }
            #pragma unroll
            for (int nt = 0; nt < 2; ++nt) {
                int nn = n0w + nt * 8 + lr;
                unsigned bh0 = *(const unsigned*)&sWh[st][nn * 72 + kb + lc2];
                unsigned bh1 = *(const unsigned*)&sWh[st][nn * 72 + kb + 8 + lc2];
                unsigned bl0 = *(const unsigned*)&sWl[st][nn * 72 + kb + lc2];
                unsigned bl1 = *(const unsigned*)&sWl[st][nn * 72 + kb + 8 + lc2];
                mma16816(C[nt], ah, bh0, bh1);
                mma16816(C[nt], ah, bl0, bl1);
                mma16816(C[nt], al, bh0, bh1);
            }
        }
    };

    issue(0, 0); issue(1, 1);
    for (int ch = 0; ch < 31; ++ch) {
        CPA_WAIT(1);
        __syncthreads();
        compute(ch & 1);
        __syncthreads();
        if (ch + 2 < 32) issue(ch + 2, ch & 1);
    }
    CPA_WAIT(0);
    __syncthreads();
    compute(1);

    // epilogue: raw gate sums (biases added in k_point)
    #pragma unroll
    for (int nt = 0; nt < 2; ++nt) {
        int j = j0 + n0w + nt * 8 + lc2;
        int b0r = m0 + lr, b1r = b0r + 8;
        g_gates[(size_t)b0r * GG + j]     = C[nt][0];
        g_gates[(size_t)b0r * GG + j + 1] = C[nt][1];
        g_gates[(size_t)b1r * GG + j]     = C[nt][2];
        g_gates[(size_t)b1r * GG + j + 1] = C[nt][3];
    }
}

// ---------------- LSTM pointwise + h split + copy-score reduction ----------------
__global__ void k_point(const float* __restrict__ Wc,
                        const float* __restrict__ bih,
                        const float* __restrict__ bhh,
                        const float* __restrict__ bc) {
    int b = blockIdx.x, tid = threadIdx.x;
    int jj = tid * 4;

    float4 gate[4];   // i, f, g, o
    #pragma unroll
    for (int g4 = 0; g4 < 4; ++g4) {
        int o = g4 * 1024 + jj;
        float4 b1 = *(const float4*)(bih + o);
        float4 b2 = *(const float4*)(bhh + o);
        float4 p  = *(const float4*)(g_gates + (size_t)b * GG + o);
        gate[g4] = make_float4(p.x + b1.x + b2.x, p.y + b1.y + b2.y,
                               p.z + b1.z + b2.z, p.w + b1.w + b2.w);
    }
    float4 iv = gate[0], fv = gate[1], gv = gate[2], ov = gate[3];
    float4 cv = *(const float4*)&g_c[(size_t)b * DD + jj];
    float4 wv = *(const float4*)&Wc[jj];

    float c0 = sigf(fv.x) * cv.x + sigf(iv.x) * tanhf(gv.x);
    float c1 = sigf(fv.y) * cv.y + sigf(iv.y) * tanhf(gv.y);
    float c2 = sigf(fv.z) * cv.z + sigf(iv.z) * tanhf(gv.z);
    float c3 = sigf(fv.w) * cv.w + sigf(iv.w) * tanhf(gv.w);
    float h0 = sigf(ov.x) * tanhf(c0);
    float h1 = sigf(ov.y) * tanhf(c1);
    float h2 = sigf(ov.z) * tanhf(c2);
    float h3 = sigf(ov.w) * tanhf(c3);

    *(float4*)&g_c[(size_t)b * DD + jj] = make_float4(c0, c1, c2, c3);

    // split h into bf16 hi/lo at A columns [1024:2048]
    __nv_bfloat16 hh, hl;
    size_t o = (size_t)b * 2048 + 1024 + jj;
    split2(h0, hh, hl); g_Ah[o]   = hh; g_Al[o]   = hl;
    split2(h1, hh, hl); g_Ah[o+1] = hh; g_Al[o+1] = hl;
    split2(h2, hh, hl); g_Ah[o+2] = hh; g_Al[o+2] = hl;
    split2(h3, hh, hl); g_Ah[o+3] = hh; g_Al[o+3] = hl;

    float p = h0 * wv.x + h1 * wv.y + h2 * wv.z + h3 * wv.w;
    __shared__ float sr[256];
    sr[tid] = p; __syncthreads();
    for (int s = 128; s > 0; s >>= 1) {
        if (tid < s) sr[tid] += sr[tid + s];
        __syncthreads();
    }
    if (tid == 0) {
        float st = bc[0];
        #pragma unroll
        for (int i = 0; i < 8; ++i) st += g_selp[b * 8 + i];
        g_cs[b] = sr[0] + st;
    }
}

// ---------------- logits^T = Wo_tile @ h^T (mma.sync, warp -> n8 batch slice) ------
// 148 blocks x 256 threads (one block per SM). Block tile: 224 vocab rows x 64 batch.
// Each warp: ONE n8 batch slice (= warp id), ALL 14 m16 vocab tiles.
// K chunks of 32 halves, 4 stages, one __syncthreads per chunk.
// Stage layout (46080 B): Whi 17920 | Wlo 17920 | Hhi 5120 | Hlo 5120.
__global__ void __launch_bounds__(256) k_logits(const float* __restrict__ bo,
                                                float* __restrict__ out,
                                                int t, int T) {
    extern __shared__ __align__(16) char dynsm[];
    __shared__ float sbo_s[224];
    __shared__ float scs[64];
    __shared__ unsigned long long sred[8 * 64];

    const int tid = threadIdx.x;
    const int lane = tid & 31, warp = tid >> 5;
    const int lr = lane >> 2;
    const int jj = lane & 7, g = lane >> 3;
    const int j0 = blockIdx.x * 224;
    const unsigned smb = smem_u32(dynsm);
    const unsigned STG_SZ = 46080;

    if (tid < 224) sbo_s[tid] = (j0 + tid < VV) ? bo[j0 + tid] : 0.0f;
    if (tid < 64) scs[tid] = g_cs[tid];

    // ldmatrix byte offsets
    const unsigned baseA = (unsigned)((jj + (g & 1) * 8) * 80 + (g >> 1) * 16);
    const unsigned byteB = (unsigned)((8 * warp + jj) * 80 + ((lane >> 3) & 1) * 16);

    float C[14][4] = {};

    auto issue = [&](int ch, int st) {
        const int k0 = ch * 32;                 // halves
        const unsigned sb = smb + (unsigned)st * STG_SZ;
        #pragma unroll
        for (int i = 0; i < 4; ++i) {           // W: 224 rows x 4 parts = 896 cp16
            int c = tid + 256 * i;
            if (c < 896) {
                int row = c >> 2, part = c & 3;
                unsigned d = (unsigned)(row * 80 + part * 16);
                size_t gsrc = (size_t)(j0 + row) * DD + k0 + part * 8;
                cpa16(sb + d,         g_Wo_hi + gsrc);
                cpa16(sb + 17920 + d, g_Wo_lo + gsrc);
            }
        }
        {                                       // h: 64 rows x 4 parts = 256 cp16
            int row = tid >> 2, part = tid & 3;
            unsigned d = (unsigned)(row * 80 + part * 16);
            size_t gsrc = (size_t)row * 2048 + 1024 + k0 + part * 8;
            cpa16(sb + 35840 + d, g_Ah + gsrc);
            cpa16(sb + 40960 + d, g_Al + gsrc);
        }
        CPA_COMMIT();
    };

    auto compute = [&](int st) {
        const unsigned sWH = smb + (unsigned)st * STG_SZ;
        const unsigned sWL = sWH + 17920;
        const unsigned sHH = sWH + 35840;
        const unsigned sHL = sWH + 40960;
        #pragma unroll
        for (int k16 = 0; k16 < 2; ++k16) {
            const unsigned ko = (unsigned)(k16 * 32);   // 16 halves = 32 bytes
            unsigned bh0, bh1, bl0, bl1;
            ldsm2(bh0, bh1, sHH + byteB + ko);
            ldsm2(bl0, bl1, sHL + byteB + ko);
            #pragma unroll
            for (int mt = 0; mt < 14; ++mt) {
                unsigned ah[4], al[4];
                ldsm4(ah[0], ah[1], ah[2], ah[3], sWH + baseA + (unsigned)(mt * 1280) + ko);
                ldsm4(al[0], al[1], al[2], al[3], sWL + baseA + (unsigned)(mt * 1280) + ko);
                mma16816(C[mt], ah, bh0, bh1);
                mma16816(C[mt], ah, bl0, bl1);
                mma16816(C[mt], al, bh0, bh1);
            }
        }
    };

    issue(0, 0); issue(1, 1); issue(2, 2);
    for (int ch = 0; ch < 32; ++ch) {
        if (ch < 30)      { CPA_WAIT(2); }
        else if (ch == 30){ CPA_WAIT(1); }
        else              { CPA_WAIT(0); }
        __syncthreads();
        if (ch + 3 < 32) issue(ch + 3, (ch + 3) & 3);
        compute(ch & 3);
    }
    __syncthreads();                            // before smem reuse

    // transpose via smem: st_t[vocab_local(224)][batch(64)] stride 65
    float* st_t = (float*)dynsm;
    const int bb = warp * 8 + (lane & 3) * 2;   // batch pair this thread holds
    const float csb0 = scs[bb], csb1 = scs[bb + 1];
    #pragma unroll
    for (int mt = 0; mt < 14; ++mt) {
        int r0 = mt * 16 + lr, r1 = r0 + 8;
        float bo0 = sbo_s[r0], bo1 = sbo_s[r1];
        st_t[r0 * 65 + bb]     = C[mt][0] + bo0 + csb0;
        st_t[r0 * 65 + bb + 1] = C[mt][1] + bo0 + csb1;
        st_t[r1 * 65 + bb]     = C[mt][2] + bo1 + csb0;
        st_t[r1 * 65 + bb + 1] = C[mt][3] + bo1 + csb1;
    }
    __syncthreads();

    // coalesced out writes + per-block argmax candidates (guard padded rows)
    const unsigned jg = (unsigned)(j0 + tid);
    const bool valid = (tid < 224) && (jg < (unsigned)VV);
    for (int b = 0; b < 64; ++b) {
        unsigned long long key = 0ull;
        if (valid) {
            float v = st_t[tid * 65 + b];
            out[((size_t)b * T + t) * VV + jg] = v;
            key = ((unsigned long long)enc_f(v) << 32)
                | (unsigned long long)(0xFFFFFFFFu - jg);
        }
        #pragma unroll
        for (int off = 16; off > 0; off >>= 1) {
            unsigned long long o = __shfl_down_sync(0xFFFFFFFFu, key, off);
            if (o > key) key = o;
        }
        if (lane == 0) sred[warp * 64 + b] = key;
    }
    __syncthreads();
    if (tid < 64) {
        unsigned long long m = sred[tid];
        #pragma unroll
        for (int w = 1; w < 8; ++w) {
            unsigned long long v = sred[w * 64 + tid];
            if (v > m) m = v;
        }
        g_cand[(size_t)blockIdx.x * BB + tid] = m;
    }
}

// ---------------- launch ----------------
extern "C" void kernel_launch(void* const* d_in, const int* in_sizes, int n_in,
                              void* d_out, int out_size) {
    const float* selected = (const float*)d_in[0];
    const float* emb_W    = (const float*)d_in[1];
    const float* W_ih     = (const float*)d_in[2];
    const float* W_hh     = (const float*)d_in[3];
    const float* b_ih     = (const float*)d_in[4];
    const float* b_hh     = (const float*)d_in[5];
    const float* Wc       = (const float*)d_in[6];
    const float* bc       = (const float*)d_in[7];
    const float* Wo       = (const float*)d_in[8];
    const float* bo       = (const float*)d_in[9];
    float* out = (float*)d_out;

    int T = out_size / (BB * VV);   // = max_len = 50
    const int SMEM_L = 4 * 46080;   // 184320 B dynamic

    cudaFuncSetAttribute(k_logits, cudaFuncAttributeMaxDynamicSharedMemorySize, SMEM_L);

    k_split_wo<<<((size_t)VP * DD / 4 + 255) / 256, 256>>>(Wo);
    k_split_wg<<<(GG * 2048 / 4 + 255) / 256, 256>>>(W_ih, W_hh);
    k_init<<<(BB * 2048 + 255) / 256, 256>>>();
    k_selterm1<<<BB * 8, 128>>>(selected, Wc);
    for (int t = 0; t < T; ++t) {
        k_tok<<<BB, 256>>>(emb_W, t);
        k_gates<<<GG / 32, 256>>>();
        k_point<<<BB, 256>>>(Wc, b_ih, b_hh, bc);
        k_logits<<<NTL, 256, SMEM_L>>>(bo, out, t, T);
    }
}

// round 15
// speedup vs baseline: 1.1330x; 1.1330x over previous
#include <cuda_runtime.h>
#include <cuda_bf16.h>
#include <math.h>

// Problem constants (shapes fixed for this problem instance)
#define BB 64           // batch
#define DD 1024         // hidden dim
#define VV 32000        // vocab
#define GG 4096         // 4*D
#define SS 128          // selected seq len
#define NTL 125         // logits blocks (256 vocab rows each)

// ---------------- persistent device scratch (no runtime allocs) ----------------
__device__ float g_c[BB * DD];
__device__ float g_gates[BB * GG];
__device__ float g_cs[BB];
__device__ float g_selp[BB * 8];
__device__ unsigned long long g_cand[NTL * BB];

// split-bf16 operands
__device__ __nv_bfloat16 g_Ah[BB * 2048];       // [b][0:1024]=emb, [1024:2048]=h
__device__ __nv_bfloat16 g_Al[BB * 2048];
__device__ __nv_bfloat16 g_Wo_hi[VV * DD];
__device__ __nv_bfloat16 g_Wo_lo[VV * DD];
__device__ __nv_bfloat16 g_Wg_hi[GG * 2048];    // concat(W_ih | W_hh) along K
__device__ __nv_bfloat16 g_Wg_lo[GG * 2048];

// ---------------- helpers ----------------
__device__ __forceinline__ unsigned enc_f(float f) {
    unsigned u = __float_as_uint(f);
    return (u & 0x80000000u) ? ~u : (u | 0x80000000u);
}
__device__ __forceinline__ float sigf(float x) { return 1.0f / (1.0f + expf(-x)); }

__device__ __forceinline__ void cpa8(unsigned s, const void* g) {
    asm volatile("cp.async.ca.shared.global [%0], [%1], 8;" :: "r"(s), "l"(g));
}
__device__ __forceinline__ void cpa16(unsigned s, const void* g) {
    asm volatile("cp.async.cg.shared.global [%0], [%1], 16;" :: "r"(s), "l"(g));
}
#define CPA_COMMIT() asm volatile("cp.async.commit_group;")
#define CPA_WAIT(n)  asm volatile("cp.async.wait_group %0;" :: "n"(n))

__device__ __forceinline__ void mma16816(float* c, const unsigned* a,
                                         unsigned b0, unsigned b1) {
    asm volatile(
        "mma.sync.aligned.m16n8k16.row.col.f32.bf16.bf16.f32 "
        "{%0,%1,%2,%3}, {%4,%5,%6,%7}, {%8,%9}, {%0,%1,%2,%3};"
        : "+f"(c[0]), "+f"(c[1]), "+f"(c[2]), "+f"(c[3])
        : "r"(a[0]), "r"(a[1]), "r"(a[2]), "r"(a[3]), "r"(b0), "r"(b1));
}

__device__ __forceinline__ void ldsm4(unsigned& r0, unsigned& r1,
                                      unsigned& r2, unsigned& r3, unsigned addr) {
    asm volatile("ldmatrix.sync.aligned.m8n8.x4.shared.b16 {%0,%1,%2,%3}, [%4];"
                 : "=r"(r0), "=r"(r1), "=r"(r2), "=r"(r3) : "r"(addr));
}

__device__ __forceinline__ void split2(float x, __nv_bfloat16& hi, __nv_bfloat16& lo) {
    hi = __float2bfloat16(x);
    lo = __float2bfloat16(x - __bfloat162float(hi));
}
__device__ __forceinline__ unsigned smem_u32(const void* p) {
    return (unsigned)__cvta_generic_to_shared(p);
}

// ---------------- weight splitting (once per call, x4 vectorized) ----------------
__global__ void k_split_wo(const float* __restrict__ Wo) {
    size_t i = ((size_t)blockIdx.x * 256 + threadIdx.x) * 4;
    if (i < (size_t)VV * DD) {
        float4 v = *(const float4*)(Wo + i);
        __nv_bfloat16 h0,l0,h1,l1,h2,l2,h3,l3;
        split2(v.x,h0,l0); split2(v.y,h1,l1); split2(v.z,h2,l2); split2(v.w,h3,l3);
        uint2 ph, pl;
        ph.x = (unsigned)__bfloat16_as_ushort(h0) | ((unsigned)__bfloat16_as_ushort(h1) << 16);
        ph.y = (unsigned)__bfloat16_as_ushort(h2) | ((unsigned)__bfloat16_as_ushort(h3) << 16);
        pl.x = (unsigned)__bfloat16_as_ushort(l0) | ((unsigned)__bfloat16_as_ushort(l1) << 16);
        pl.y = (unsigned)__bfloat16_as_ushort(l2) | ((unsigned)__bfloat16_as_ushort(l3) << 16);
        *(uint2*)(g_Wo_hi + i) = ph;
        *(uint2*)(g_Wo_lo + i) = pl;
    }
}
__global__ void k_split_wg(const float* __restrict__ Wih,
                           const float* __restrict__ Whh) {
    size_t i = ((size_t)blockIdx.x * 256 + threadIdx.x) * 4;
    if (i < (size_t)GG * 2048) {
        int j = (int)(i >> 11), k = (int)(i & 2047);
        const float* src = (k < DD) ? (Wih + (size_t)j * DD + k)
                                    : (Whh + (size_t)j * DD + k - DD);
        float4 v = *(const float4*)src;
        __nv_bfloat16 h0,l0,h1,l1,h2,l2,h3,l3;
        split2(v.x,h0,l0); split2(v.y,h1,l1); split2(v.z,h2,l2); split2(v.w,h3,l3);
        uint2 ph, pl;
        ph.x = (unsigned)__bfloat16_as_ushort(h0) | ((unsigned)__bfloat16_as_ushort(h1) << 16);
        ph.y = (unsigned)__bfloat16_as_ushort(h2) | ((unsigned)__bfloat16_as_ushort(h3) << 16);
        pl.x = (unsigned)__bfloat16_as_ushort(l0) | ((unsigned)__bfloat16_as_ushort(l1) << 16);
        pl.y = (unsigned)__bfloat16_as_ushort(l2) | ((unsigned)__bfloat16_as_ushort(l3) << 16);
        *(uint2*)(g_Wg_hi + i) = ph;
        *(uint2*)(g_Wg_lo + i) = pl;
    }
}

// ---------------- init: zero c and A buffers ----------------
__global__ void k_init() {
    int i = blockIdx.x * 256 + threadIdx.x;
    if (i < BB * DD) g_c[i] = 0.0f;
    if (i < BB * 2048) { g_Ah[i] = __float2bfloat16(0.0f); g_Al[i] = __float2bfloat16(0.0f); }
}

// ---------------- selterm partials: 512 blocks of (b, d-slice of 128) ----------------
__global__ void k_selterm1(const float* __restrict__ selected,
                           const float* __restrict__ Wc) {
    int b = blockIdx.x >> 3, s = blockIdx.x & 7, tid = threadIdx.x;  // 128 threads
    int d = s * 128 + tid;
    const float* p = selected + (size_t)b * SS * DD + d;
    float sum = 0.0f;
    #pragma unroll 4
    for (int si = 0; si < SS; ++si) sum += p[(size_t)si * DD];
    float v = Wc[DD + d] * (sum * (1.0f / (float)SS));
    __shared__ float sr[128];
    sr[tid] = v; __syncthreads();
    for (int st = 64; st > 0; st >>= 1) {
        if (tid < st) sr[tid] += sr[tid + st];
        __syncthreads();
    }
    if (tid == 0) g_selp[b * 8 + s] = sr[0];
}

// ---------------- tok: argmax reduce (t>0) + embedding gather/split ----------------
__global__ void k_tok(const float* __restrict__ emb_W, int t) {
    int b = blockIdx.x, tid = threadIdx.x;
    __shared__ unsigned long long sk[256];
    __shared__ int s_j;
    if (t == 0) {
        if (tid == 0) s_j = 0;                // tok0 = 0 (PAD row is zeros)
    } else {
        unsigned long long best = 0ull;
        for (int i = tid; i < NTL; i += 256) {
            unsigned long long v = g_cand[i * BB + b];
            if (v > best) best = v;
        }
        sk[tid] = best; __syncthreads();
        for (int s = 128; s > 0; s >>= 1) {
            if (tid < s && sk[tid + s] > sk[tid]) sk[tid] = sk[tid + s];
            __syncthreads();
        }
        if (tid == 0) s_j = (int)(0xFFFFFFFFu - (unsigned)(sk[0] & 0xFFFFFFFFull));
    }
    __syncthreads();
    int j = s_j;
    const float4 e4 = *(const float4*)(emb_W + (size_t)j * DD + tid * 4);
    __nv_bfloat16 h0, l0, h1, l1, h2, l2, h3, l3;
    split2(e4.x, h0, l0); split2(e4.y, h1, l1);
    split2(e4.z, h2, l2); split2(e4.w, h3, l3);
    size_t o = (size_t)b * 2048 + tid * 4;
    g_Ah[o] = h0; g_Ah[o+1] = h1; g_Ah[o+2] = h2; g_Ah[o+3] = h3;
    g_Al[o] = l0; g_Al[o+1] = l1; g_Al[o+2] = l2; g_Al[o+3] = l3;
}

// ---------------- gates = A @ Wg^T (split-bf16 mma.sync, 3 passes) ----------------
// 128 blocks of 64M x 32N. K=2048, chunks of 64 (stride 72 halves in smem).
__global__ void __launch_bounds__(256) k_gates() {
    const int tid = threadIdx.x;
    const int lane = tid & 31, warp = tid >> 5;
    const int lr = lane >> 2, lc2 = (lane & 3) * 2;
    const int m0 = (warp >> 1) * 16, n0w = (warp & 1) * 16;
    const int j0 = blockIdx.x * 32;

    __shared__ __align__(16) __nv_bfloat16 sWh[2][32 * 72];
    __shared__ __align__(16) __nv_bfloat16 sWl[2][32 * 72];
    __shared__ __align__(16) __nv_bfloat16 sAh[2][64 * 72];
    __shared__ __align__(16) __nv_bfloat16 sAl[2][64 * 72];

    unsigned aWh[2], aWl[2], aAh[2], aAl[2];
    #pragma unroll
    for (int s = 0; s < 2; ++s) {
        aWh[s] = smem_u32(&sWh[s][0]);
        aWl[s] = smem_u32(&sWl[s][0]);
        aAh[s] = smem_u32(&sAh[s][0]);
        aAl[s] = smem_u32(&sAl[s][0]);
    }

    float C[2][4] = {};

    auto issue = [&](int ch, int st) {
        int k0 = ch * 64;
        #pragma unroll
        for (int i = 0; i < 2; ++i) {
            int c = tid + 256 * i;           // 512 W chunks
            int row = c >> 4, part = c & 15;
            unsigned d = (unsigned)(row * 72 + part * 4) * 2;
            size_t gsrc = (size_t)(j0 + row) * 2048 + k0 + part * 4;
            cpa8(aWh[st] + d, g_Wg_hi + gsrc);
            cpa8(aWl[st] + d, g_Wg_lo + gsrc);
        }
        #pragma unroll
        for (int i = 0; i < 4; ++i) {
            int c = tid + 256 * i;           // 1024 A chunks
            int row = c >> 4, part = c & 15;
            unsigned d = (unsigned)(row * 72 + part * 4) * 2;
            size_t gsrc = (size_t)row * 2048 + k0 + part * 4;
            cpa8(aAh[st] + d, g_Ah + gsrc);
            cpa8(aAl[st] + d, g_Al + gsrc);
        }
        CPA_COMMIT();
    };
    auto compute = [&](int st) {
        #pragma unroll
        for (int k16 = 0; k16 < 4; ++k16) {
            const int kb = k16 * 16;
            unsigned ah[4], al[4];
            #pragma unroll
            for (int r = 0; r < 4; ++r) {
                int mm = m0 + lr + (r & 1) * 8;
                int kk = kb + lc2 + (r >> 1) * 8;
                ah[r] = *(const unsigned*)&sAh[st][mm * 72 + kk];
                al[r] = *(const unsigned*)&sAl[st][mm * 72 + kk];
            }
            #pragma unroll
            for (int nt = 0; nt < 2; ++nt) {
                int nn = n0w + nt * 8 + lr;
                unsigned bh0 = *(const unsigned*)&sWh[st][nn * 72 + kb + lc2];
                unsigned bh1 = *(const unsigned*)&sWh[st][nn * 72 + kb + 8 + lc2];
                unsigned bl0 = *(const unsigned*)&sWl[st][nn * 72 + kb + lc2];
                unsigned bl1 = *(const unsigned*)&sWl[st][nn * 72 + kb + 8 + lc2];
                mma16816(C[nt], ah, bh0, bh1);
                mma16816(C[nt], ah, bl0, bl1);
                mma16816(C[nt], al, bh0, bh1);
            }
        }
    };

    issue(0, 0); issue(1, 1);
    for (int ch = 0; ch < 31; ++ch) {
        CPA_WAIT(1);
        __syncthreads();
        compute(ch & 1);
        __syncthreads();
        if (ch + 2 < 32) issue(ch + 2, ch & 1);
    }
    CPA_WAIT(0);
    __syncthreads();
    compute(1);

    // epilogue: raw gate sums (biases added in k_point)
    #pragma unroll
    for (int nt = 0; nt < 2; ++nt) {
        int j = j0 + n0w + nt * 8 + lc2;
        int b0r = m0 + lr, b1r = b0r + 8;
        g_gates[(size_t)b0r * GG + j]     = C[nt][0];
        g_gates[(size_t)b0r * GG + j + 1] = C[nt][1];
        g_gates[(size_t)b1r * GG + j]     = C[nt][2];
        g_gates[(size_t)b1r * GG + j + 1] = C[nt][3];
    }
}

// ---------------- LSTM pointwise + h split + copy-score reduction ----------------
__global__ void k_point(const float* __restrict__ Wc,
                        const float* __restrict__ bih,
                        const float* __restrict__ bhh,
                        const float* __restrict__ bc) {
    int b = blockIdx.x, tid = threadIdx.x;
    int jj = tid * 4;

    float4 gate[4];   // i, f, g, o
    #pragma unroll
    for (int g4 = 0; g4 < 4; ++g4) {
        int o = g4 * 1024 + jj;
        float4 b1 = *(const float4*)(bih + o);
        float4 b2 = *(const float4*)(bhh + o);
        float4 p  = *(const float4*)(g_gates + (size_t)b * GG + o);
        gate[g4] = make_float4(p.x + b1.x + b2.x, p.y + b1.y + b2.y,
                               p.z + b1.z + b2.z, p.w + b1.w + b2.w);
    }
    float4 iv = gate[0], fv = gate[1], gv = gate[2], ov = gate[3];
    float4 cv = *(const float4*)&g_c[(size_t)b * DD + jj];
    float4 wv = *(const float4*)&Wc[jj];

    float c0 = sigf(fv.x) * cv.x + sigf(iv.x) * tanhf(gv.x);
    float c1 = sigf(fv.y) * cv.y + sigf(iv.y) * tanhf(gv.y);
    float c2 = sigf(fv.z) * cv.z + sigf(iv.z) * tanhf(gv.z);
    float c3 = sigf(fv.w) * cv.w + sigf(iv.w) * tanhf(gv.w);
    float h0 = sigf(ov.x) * tanhf(c0);
    float h1 = sigf(ov.y) * tanhf(c1);
    float h2 = sigf(ov.z) * tanhf(c2);
    float h3 = sigf(ov.w) * tanhf(c3);

    *(float4*)&g_c[(size_t)b * DD + jj] = make_float4(c0, c1, c2, c3);

    // split h into bf16 hi/lo at A columns [1024:2048]
    __nv_bfloat16 hh, hl;
    size_t o = (size_t)b * 2048 + 1024 + jj;
    split2(h0, hh, hl); g_Ah[o]   = hh; g_Al[o]   = hl;
    split2(h1, hh, hl); g_Ah[o+1] = hh; g_Al[o+1] = hl;
    split2(h2, hh, hl); g_Ah[o+2] = hh; g_Al[o+2] = hl;
    split2(h3, hh, hl); g_Ah[o+3] = hh; g_Al[o+3] = hl;

    float p = h0 * wv.x + h1 * wv.y + h2 * wv.z + h3 * wv.w;
    __shared__ float sr[256];
    sr[tid] = p; __syncthreads();
    for (int s = 128; s > 0; s >>= 1) {
        if (tid < s) sr[tid] += sr[tid + s];
        __syncthreads();
    }
    if (tid == 0) {
        float st = bc[0];
        #pragma unroll
        for (int i = 0; i < 8; ++i) st += g_selp[b * 8 + i];
        g_cs[b] = sr[0] + st;
    }
}

// ---------------- logits^T = Wo_tile @ h^T (mma.sync, W as A-operand) ----------------
// 125 blocks x 256 threads. Block tile: 256 vocab rows (M) x 64 batch (N).
// Warp w -> m rows [w*32, w*32+32) (2 m16 tiles), all 64 batch as 8 n8 tiles.
// K chunks of 32 halves, 4 stages, ONE __syncthreads per chunk.
// Stage layout (51200B): Whi 20480 | Wlo 20480 | Hhi 5120 | Hlo 5120.
__global__ void __launch_bounds__(256) k_logits(const float* __restrict__ bo,
                                                float* __restrict__ out,
                                                int t, int T) {
    extern __shared__ __align__(16) char dynsm[];
    __shared__ float sbo_s[256];
    __shared__ float scs[64];
    __shared__ unsigned long long sred[8 * 64];

    const int tid = threadIdx.x;
    const int lane = tid & 31, warp = tid >> 5;
    const int lr = lane >> 2;
    const int jj = lane & 7, g = lane >> 3;
    const int j0 = blockIdx.x * 256;
    const unsigned smb = smem_u32(dynsm);
    const unsigned STG_SZ = 51200;

    sbo_s[tid] = bo[j0 + tid];
    if (tid < 64) scs[tid] = g_cs[tid];

    // per-lane ldmatrix byte offsets (within operand region)
    unsigned byteA[2];   // [mtile]
    #pragma unroll
    for (int mt = 0; mt < 2; ++mt) {
        int rowA = warp * 32 + mt * 16 + jj + (g & 1) * 8;
        byteA[mt] = (unsigned)(rowA * 80 + (g >> 1) * 16);
    }
    const unsigned byteB = (unsigned)((jj + (g >> 1) * 8) * 80 + (g & 1) * 16);

    float C[2][8][4] = {};

    auto issue = [&](int ch, int st) {
        const int k0 = ch * 32;                 // halves
        const unsigned sb = smb + (unsigned)st * STG_SZ;
        #pragma unroll
        for (int i = 0; i < 4; ++i) {           // W: 1024 cp16 per operand
            int c = tid + 256 * i;
            int row = c >> 2, part = c & 3;
            unsigned d = (unsigned)(row * 80 + part * 16);
            size_t gsrc = (size_t)(j0 + row) * DD + k0 + part * 8;
            cpa16(sb + d,         g_Wo_hi + gsrc);
            cpa16(sb + 20480 + d, g_Wo_lo + gsrc);
        }
        {                                       // h: 256 cp16 per operand
            int row = tid >> 2, part = tid & 3;
            unsigned d = (unsigned)(row * 80 + part * 16);
            size_t gsrc = (size_t)row * 2048 + 1024 + k0 + part * 8;
            cpa16(sb + 40960 + d, g_Ah + gsrc);
            cpa16(sb + 46080 + d, g_Al + gsrc);
        }
        CPA_COMMIT();
    };

    auto compute = [&](int st) {
        const unsigned sWH = smb + (unsigned)st * STG_SZ;
        const unsigned sWL = sWH + 20480;
        const unsigned sHH = sWH + 40960;
        const unsigned sHL = sWH + 46080;
        #pragma unroll
        for (int k16 = 0; k16 < 2; ++k16) {
            const unsigned ko = (unsigned)(k16 * 32);   // 16 halves = 32 bytes
            unsigned ah[2][4], al[2][4];
            #pragma unroll
            for (int mt = 0; mt < 2; ++mt) {
                ldsm4(ah[mt][0], ah[mt][1], ah[mt][2], ah[mt][3], sWH + byteA[mt] + ko);
                ldsm4(al[mt][0], al[mt][1], al[mt][2], al[mt][3], sWL + byteA[mt] + ko);
            }
            unsigned bh[8][2], bl[8][2];
            #pragma unroll
            for (int nb4 = 0; nb4 < 4; ++nb4) {
                unsigned off = byteB + (unsigned)(nb4 * 16 * 80) + ko;
                ldsm4(bh[nb4*2][0], bh[nb4*2][1], bh[nb4*2+1][0], bh[nb4*2+1][1], sHH + off);
                ldsm4(bl[nb4*2][0], bl[nb4*2][1], bl[nb4*2+1][0], bl[nb4*2+1][1], sHL + off);
            }
            #pragma unroll
            for (int mt = 0; mt < 2; ++mt)
                #pragma unroll
                for (int n8 = 0; n8 < 8; ++n8) {
                    mma16816(C[mt][n8], ah[mt], bh[n8][0], bh[n8][1]);
                    mma16816(C[mt][n8], ah[mt], bl[n8][0], bl[n8][1]);
                    mma16816(C[mt][n8], al[mt], bh[n8][0], bh[n8][1]);
                }
        }
    };

    issue(0, 0); issue(1, 1); issue(2, 2);
    for (int ch = 0; ch < 32; ++ch) {
        if (ch < 30)       { CPA_WAIT(2); }
        else if (ch == 30) { CPA_WAIT(1); }
        else               { CPA_WAIT(0); }
        __syncthreads();
        if (ch + 3 < 32) issue(ch + 3, (ch + 3) & 3);
        compute(ch & 3);
    }
    __syncthreads();                            // before smem reuse

    // transpose via smem: st_t[j_local(256)][batch(64)] stride 65
    float* st_t = (float*)dynsm;
    const int bb0 = (lane & 3) * 2;
    #pragma unroll
    for (int mt = 0; mt < 2; ++mt) {
        int jl0 = warp * 32 + mt * 16 + lr, jl1 = jl0 + 8;
        float bo0 = sbo_s[jl0], bo1 = sbo_s[jl1];
        #pragma unroll
        for (int n8 = 0; n8 < 8; ++n8) {
            int b = n8 * 8 + bb0;
            st_t[jl0 * 65 + b]     = C[mt][n8][0] + bo0 + scs[b];
            st_t[jl0 * 65 + b + 1] = C[mt][n8][1] + bo0 + scs[b + 1];
            st_t[jl1 * 65 + b]     = C[mt][n8][2] + bo1 + scs[b];
            st_t[jl1 * 65 + b + 1] = C[mt][n8][3] + bo1 + scs[b + 1];
        }
    }
    __syncthreads();

    // coalesced out writes + per-block argmax candidates
    const unsigned jg = (unsigned)(j0 + tid);
    for (int b = 0; b < 64; ++b) {
        float v = st_t[tid * 65 + b];
        out[((size_t)b * T + t) * VV + jg] = v;
        unsigned long long key = ((unsigned long long)enc_f(v) << 32)
                               | (unsigned long long)(0xFFFFFFFFu - jg);
        #pragma unroll
        for (int off = 16; off > 0; off >>= 1) {
            unsigned long long o = __shfl_down_sync(0xFFFFFFFFu, key, off);
            if (o > key) key = o;
        }
        if (lane == 0) sred[warp * 64 + b] = key;
    }
    __syncthreads();
    if (tid < 64) {
        unsigned long long m = sred[tid];
        #pragma unroll
        for (int w = 1; w < 8; ++w) {
            unsigned long long v = sred[w * 64 + tid];
            if (v > m) m = v;
        }
        g_cand[(size_t)blockIdx.x * BB + tid] = m;
    }
}

// ---------------- launch ----------------
extern "C" void kernel_launch(void* const* d_in, const int* in_sizes, int n_in,
                              void* d_out, int out_size) {
    const float* selected = (const float*)d_in[0];
    const float* emb_W    = (const float*)d_in[1];
    const float* W_ih     = (const float*)d_in[2];
    const float* W_hh     = (const float*)d_in[3];
    const float* b_ih     = (const float*)d_in[4];
    const float* b_hh     = (const float*)d_in[5];
    const float* Wc       = (const float*)d_in[6];
    const float* bc       = (const float*)d_in[7];
    const float* Wo       = (const float*)d_in[8];
    const float* bo       = (const float*)d_in[9];
    float* out = (float*)d_out;

    int T = out_size / (BB * VV);   // = max_len = 50
    const int SMEM_L = 4 * 51200;   // 204800 B dynamic

    cudaFuncSetAttribute(k_logits, cudaFuncAttributeMaxDynamicSharedMemorySize, SMEM_L);

    k_split_wo<<<(VV * DD / 4 + 255) / 256, 256>>>(Wo);
    k_split_wg<<<(GG * 2048 / 4 + 255) / 256, 256>>>(W_ih, W_hh);
    k_init<<<(BB * 2048 + 255) / 256, 256>>>();
    k_selterm1<<<BB * 8, 128>>>(selected, Wc);
    for (int t = 0; t < T; ++t) {
        k_tok<<<BB, 256>>>(emb_W, t);
        k_gates<<<GG / 32, 256>>>();
        k_point<<<BB, 256>>>(Wc, b_ih, b_hh, bc);
        k_logits<<<NTL, 256, SMEM_L>>>(bo, out, t, T);
    }
}